// round 14
// baseline (speedup 1.0000x reference)
#include <cuda_runtime.h>
#include <cuda_fp16.h>

#define MAXN 100000
#define MAXE 1600000
#define SB 512

typedef unsigned long long u64t;

// packed f32x2 ops (sm_103a double-rate FP32 — only via PTX)
#define FMA2(d, a, b, c) \
    asm("fma.rn.f32x2 %0, %1, %2, %3;" : "=l"(d) : "l"(a), "l"(b), "l"(c))
#define PK2(d, lo, hi) \
    asm("mov.b64 %0, {%1, %2};" : "=l"(d) : "r"(__float_as_uint(lo)), "r"(__float_as_uint(hi)))

__device__ __forceinline__ float lo2(u64t v) { return __uint_as_float((unsigned)(v & 0xffffffffu)); }
__device__ __forceinline__ float hi2(u64t v) { return __uint_as_float((unsigned)(v >> 32)); }

__device__ __forceinline__ unsigned h2bits(__half2 h) {
    union { __half2 h; unsigned u; } cv; cv.h = h; return cv.u;
}
__device__ __forceinline__ __half2 bits2h(unsigned u) {
    union { unsigned u; __half2 h; } cv; cv.u = u; return cv.h;
}

// Scratch (device globals — no allocation allowed). g_deg/g_ticket are
// zero at module load; k_fill re-zeroes them each replay (tail-zeroing).
__device__ int     g_any = 0;          // sticky: 1 => edge buffer is int32
__device__ int     g_ticket;
__device__ int     g_deg[MAXN];
__device__ float   g_dinv[MAXN];
__device__ int     g_rank[MAXE];
__device__ int     g_csr[MAXE];
__device__ int     g_rowstart[MAXN];
__device__ int     g_rowend[MAXN];
__device__ __half2 g_xwh[MAXN * 32];   // x @ W1 (fp16); dinv-scaled by k_scale
__device__ __half2 g_hh [MAXN * 32];   // hidden after relu (fp16)
__device__ __half2 g_hwh[MAXN * 8];    // (h @ W2) * dinv[row], fp16 messages

// ---------------------------------------------------------------------------
// detect: sticky dtype detect (int64 LE => odd 32-bit words all zero)
__global__ void k_detect(const unsigned* __restrict__ w) {
    int i = blockIdx.x * blockDim.x + threadIdx.x;
    if (i < 2048 && w[2 * i + 1] != 0u) atomicOr(&g_any, 1);
}

// deg (x4 MLP): 4 edges/thread — vector dst decode, 4 atomics, int4 rank store
__global__ void k_deg4(const void* __restrict__ eiv, int e, int n) {
    int q = blockIdx.x * blockDim.x + threadIdx.x;
    if (q * 4 >= e) return;
    int d0, d1, d2, d3;
    if (g_any == 0) {
        const longlong4* p = (const longlong4*)((const long long*)eiv + e);
        longlong4 v = p[q];
        d0 = (int)v.x; d1 = (int)v.y; d2 = (int)v.z; d3 = (int)v.w;
    } else {
        const int4* p = (const int4*)((const int*)eiv + e);
        int4 v = p[q];
        d0 = v.x; d1 = v.y; d2 = v.z; d3 = v.w;
    }
    int4 r;
    r.x = ((unsigned)d0 < (unsigned)n) ? atomicAdd(&g_deg[d0], 1) : -1;
    r.y = ((unsigned)d1 < (unsigned)n) ? atomicAdd(&g_deg[d1], 1) : -1;
    r.z = ((unsigned)d2 < (unsigned)n) ? atomicAdd(&g_deg[d2], 1) : -1;
    r.w = ((unsigned)d3 < (unsigned)n) ? atomicAdd(&g_deg[d3], 1) : -1;
    *reinterpret_cast<int4*>(&g_rank[q * 4]) = r;
}

__global__ void k_deg1(const void* __restrict__ eiv, int e, int n) {
    int i = blockIdx.x * blockDim.x + threadIdx.x;
    if (i >= e) return;
    int d;
    if (g_any == 0) d = (int)((const long long*)eiv)[(long long)e + i];
    else            d = ((const int*)eiv)[e + i];
    if ((unsigned)d < (unsigned)n) g_rank[i] = atomicAdd(&g_deg[d], 1);
    else                           g_rank[i] = -1;
}

// scan: block-local scan + one atomic ticket per block; writes rowstart AND
// rowend (deg has no readers after this kernel -> fill can zero it)
__global__ void k_scan(int n) {
    __shared__ int sh[SB];
    __shared__ int s_base;
    int t = threadIdx.x;
    int g = blockIdx.x * SB + t;
    int deg = (g < n) ? g_deg[g] : 0;
    sh[t] = deg;
    __syncthreads();
    for (int off = 1; off < SB; off <<= 1) {
        int tmp = (t >= off) ? sh[t - off] : 0;
        __syncthreads();
        if (t >= off) sh[t] += tmp;
        __syncthreads();
    }
    int incl = sh[t];
    if (t == SB - 1) s_base = atomicAdd(&g_ticket, incl);
    __syncthreads();
    if (g < n) {
        int end = s_base + incl;
        g_rowstart[g] = end - deg;
        g_rowend[g]   = end;
        g_dinv[g]     = rsqrtf((float)deg + 1.0f);
    }
}

// fill (x4 MLP) + tail-zero deg/ticket for next replay  (profiled slot #4)
__global__ void k_fill4(const void* __restrict__ eiv, int e, int n) {
    int q = blockIdx.x * blockDim.x + threadIdx.x;
    if (q < n) g_deg[q] = 0;            // e/4 = 400k threads cover n = 100k
    if (q == 0) g_ticket = 0;
    if (q * 4 >= e) return;
    int4 r = *reinterpret_cast<const int4*>(&g_rank[q * 4]);
    int s0, s1, s2, s3, d0, d1, d2, d3;
    if (g_any == 0) {
        const longlong4* ps = (const longlong4*)eiv;
        const longlong4* pd = (const longlong4*)((const long long*)eiv + e);
        longlong4 vs = ps[q];
        longlong4 vd = pd[q];
        s0 = (int)vs.x; s1 = (int)vs.y; s2 = (int)vs.z; s3 = (int)vs.w;
        d0 = (int)vd.x; d1 = (int)vd.y; d2 = (int)vd.z; d3 = (int)vd.w;
    } else {
        const int4* ps = (const int4*)eiv;
        const int4* pd = (const int4*)((const int*)eiv + e);
        int4 vs = ps[q];
        int4 vd = pd[q];
        s0 = vs.x; s1 = vs.y; s2 = vs.z; s3 = vs.w;
        d0 = vd.x; d1 = vd.y; d2 = vd.z; d3 = vd.w;
    }
    if ((unsigned)s0 >= (unsigned)n) s0 = 0;
    if ((unsigned)s1 >= (unsigned)n) s1 = 0;
    if ((unsigned)s2 >= (unsigned)n) s2 = 0;
    if ((unsigned)s3 >= (unsigned)n) s3 = 0;
    int b0 = (r.x >= 0) ? g_rowstart[d0] : 0;
    int b1 = (r.y >= 0) ? g_rowstart[d1] : 0;
    int b2 = (r.z >= 0) ? g_rowstart[d2] : 0;
    int b3 = (r.w >= 0) ? g_rowstart[d3] : 0;
    if (r.x >= 0) g_csr[b0 + r.x] = s0;
    if (r.y >= 0) g_csr[b1 + r.y] = s1;
    if (r.z >= 0) g_csr[b2 + r.z] = s2;
    if (r.w >= 0) g_csr[b3 + r.w] = s3;
}

__global__ void k_fill1(const void* __restrict__ eiv, int e, int n) {
    int i = blockIdx.x * blockDim.x + threadIdx.x;
    if (i < n) g_deg[i] = 0;
    if (i == 0) g_ticket = 0;
    if (i >= e) return;
    int r = g_rank[i];
    if (r < 0) return;
    int s, d;
    if (g_any == 0) {
        const long long* ei = (const long long*)eiv;
        s = (int)ei[i];
        d = (int)ei[(long long)e + i];
    } else {
        const int* ei = (const int*)eiv;
        s = ei[i];
        d = ei[e + i];
    }
    if ((unsigned)s >= (unsigned)n) s = 0;
    g_csr[g_rowstart[d] + r] = s;
}

// GEMM1 via packed f32x2; stores UNSCALED fp16 (no dinv dependency)
__global__ void __launch_bounds__(256) k_gemm1(const float* __restrict__ x,
                                               const float* __restrict__ W, int n) {
    __shared__ float2 Xt2[64][66];
    __shared__ float4 Wsh4[64 * 16];
    int tx = threadIdx.x;
    int ty = threadIdx.y;
    int tid = ty * 16 + tx;
    int row0 = blockIdx.x * 128;
    const float4* x4 = (const float4*)x;
    const float4* W4 = (const float4*)W;
    for (int i = tid; i < 1024; i += 256) Wsh4[i] = W4[i];
    float4 z = make_float4(0.f, 0.f, 0.f, 0.f);
    for (int i = tid; i < 1024; i += 256) {
        int p = i >> 4, c4 = i & 15;
        int r = row0 + 2 * p;
        float4 v0 = (r     < n) ? x4[(r)     * 16 + c4] : z;
        float4 v1 = (r + 1 < n) ? x4[(r + 1) * 16 + c4] : z;
        Xt2[c4 * 4 + 0][p] = make_float2(v0.x, v1.x);
        Xt2[c4 * 4 + 1][p] = make_float2(v0.y, v1.y);
        Xt2[c4 * 4 + 2][p] = make_float2(v0.z, v1.z);
        Xt2[c4 * 4 + 3][p] = make_float2(v0.w, v1.w);
    }
    __syncthreads();
    u64t acc[4][4];
    #pragma unroll
    for (int p = 0; p < 4; p++)
        #pragma unroll
        for (int c = 0; c < 4; c++) acc[p][c] = 0ull;
    int pbase = ty * 4;
    #pragma unroll 16
    for (int k = 0; k < 64; k++) {
        float4 w = Wsh4[k * 16 + tx];
        u64t w0, w1, w2, w3;
        PK2(w0, w.x, w.x);
        PK2(w1, w.y, w.y);
        PK2(w2, w.z, w.z);
        PK2(w3, w.w, w.w);
        #pragma unroll
        for (int p = 0; p < 4; p++) {
            u64t xv = *reinterpret_cast<const u64t*>(&Xt2[k][pbase + p]);
            FMA2(acc[p][0], xv, w0, acc[p][0]);
            FMA2(acc[p][1], xv, w1, acc[p][1]);
            FMA2(acc[p][2], xv, w2, acc[p][2]);
            FMA2(acc[p][3], xv, w3, acc[p][3]);
        }
    }
    #pragma unroll
    for (int p = 0; p < 4; p++) {
        int re = row0 + 2 * (pbase + p);
        int ro = re + 1;
        if (re < n) {
            __half2 h0 = __floats2half2_rn(lo2(acc[p][0]), lo2(acc[p][1]));
            __half2 h1 = __floats2half2_rn(lo2(acc[p][2]), lo2(acc[p][3]));
            *reinterpret_cast<uint2*>(&g_xwh[re * 32 + 2 * tx]) =
                make_uint2(h2bits(h0), h2bits(h1));
        }
        if (ro < n) {
            __half2 h0 = __floats2half2_rn(hi2(acc[p][0]), hi2(acc[p][1]));
            __half2 h1 = __floats2half2_rn(hi2(acc[p][2]), hi2(acc[p][3]));
            *reinterpret_cast<uint2*>(&g_xwh[ro * 32 + 2 * tx]) =
                make_uint2(h2bits(h0), h2bits(h1));
        }
    }
}

// scale messages by dinv[row] in place (off critical path: overlaps fill)
__global__ void k_scale(int n) {
    int i = blockIdx.x * blockDim.x + threadIdx.x;
    if (i >= n * 16) return;
    int row = i >> 4;
    float di = g_dinv[row];
    uint2 v = ((uint2*)g_xwh)[i];
    float2 fa = __half22float2(bits2h(v.x));
    float2 fb = __half22float2(bits2h(v.y));
    fa.x *= di; fa.y *= di; fb.x *= di; fb.y *= di;
    ((uint2*)g_xwh)[i] = make_uint2(h2bits(__floats2half2_rn(fa.x, fa.y)),
                                    h2bits(__floats2half2_rn(fb.x, fb.y)));
}

// layer-1 aggregation: one warp per node; unroll 8 (MLP 8); fp16 hidden out
__global__ void k_agg1(const float* __restrict__ b1, int n) {
    int warp = (blockIdx.x * blockDim.x + threadIdx.x) >> 5;
    int lane = threadIdx.x & 31;
    if (warp >= n) return;
    int beg = g_rowstart[warp];
    int end = g_rowend[warp];
    float ax0 = 0.f, ay0 = 0.f, ax1 = 0.f, ay1 = 0.f;
    float ax2 = 0.f, ay2 = 0.f, ax3 = 0.f, ay3 = 0.f;
    float ax4 = 0.f, ay4 = 0.f, ax5 = 0.f, ay5 = 0.f;
    float ax6 = 0.f, ay6 = 0.f, ax7 = 0.f, ay7 = 0.f;
    int j = beg;
    for (; j + 8 <= end; j += 8) {
        int s0 = g_csr[j],     s1 = g_csr[j + 1], s2 = g_csr[j + 2], s3 = g_csr[j + 3];
        int s4 = g_csr[j + 4], s5 = g_csr[j + 5], s6 = g_csr[j + 6], s7 = g_csr[j + 7];
        float2 f0 = __half22float2(g_xwh[s0 * 32 + lane]);
        float2 f1 = __half22float2(g_xwh[s1 * 32 + lane]);
        float2 f2 = __half22float2(g_xwh[s2 * 32 + lane]);
        float2 f3 = __half22float2(g_xwh[s3 * 32 + lane]);
        float2 f4 = __half22float2(g_xwh[s4 * 32 + lane]);
        float2 f5 = __half22float2(g_xwh[s5 * 32 + lane]);
        float2 f6 = __half22float2(g_xwh[s6 * 32 + lane]);
        float2 f7 = __half22float2(g_xwh[s7 * 32 + lane]);
        ax0 += f0.x; ay0 += f0.y; ax1 += f1.x; ay1 += f1.y;
        ax2 += f2.x; ay2 += f2.y; ax3 += f3.x; ay3 += f3.y;
        ax4 += f4.x; ay4 += f4.y; ax5 += f5.x; ay5 += f5.y;
        ax6 += f6.x; ay6 += f6.y; ax7 += f7.x; ay7 += f7.y;
    }
    for (; j + 4 <= end; j += 4) {
        int s0 = g_csr[j], s1 = g_csr[j + 1], s2 = g_csr[j + 2], s3 = g_csr[j + 3];
        float2 f0 = __half22float2(g_xwh[s0 * 32 + lane]);
        float2 f1 = __half22float2(g_xwh[s1 * 32 + lane]);
        float2 f2 = __half22float2(g_xwh[s2 * 32 + lane]);
        float2 f3 = __half22float2(g_xwh[s3 * 32 + lane]);
        ax0 += f0.x; ay0 += f0.y; ax1 += f1.x; ay1 += f1.y;
        ax2 += f2.x; ay2 += f2.y; ax3 += f3.x; ay3 += f3.y;
    }
    for (; j < end; j++) {
        float2 f = __half22float2(g_xwh[g_csr[j] * 32 + lane]);
        ax0 += f.x; ay0 += f.y;
    }
    float2 self = __half22float2(g_xwh[warp * 32 + lane]);
    float di = g_dinv[warp];
    float sx = ((ax0 + ax1) + (ax2 + ax3)) + ((ax4 + ax5) + (ax6 + ax7));
    float sy = ((ay0 + ay1) + (ay2 + ay3)) + ((ay4 + ay5) + (ay6 + ay7));
    float vx = di * (sx + self.x) + b1[2 * lane];
    float vy = di * (sy + self.y) + b1[2 * lane + 1];
    vx = vx > 0.f ? vx : 0.f;
    vy = vy > 0.f ? vy : 0.f;
    g_hh[warp * 32 + lane] = __floats2half2_rn(vx, vy);
}

// GEMM2: g_hwh = fp16((h @ W2) * dinv[row]); 128-row tile, 2 rows/thread
__global__ void k_gemm2(const float* __restrict__ W, int n) {
    __shared__ float4 Wsh4[64 * 4];
    __shared__ float  Xsh[128][65];
    int tx = threadIdx.x;
    int ty = threadIdx.y;
    int tid = ty * 4 + tx;
    int row0 = blockIdx.x * 128;
    const float4* W4 = (const float4*)W;
    for (int i = tid; i < 256; i += 256) Wsh4[i] = W4[i];
    const unsigned* hh = (const unsigned*)g_hh;
    for (int i = tid; i < 4096; i += 256) {
        int r = i >> 5, c2 = i & 31;
        float2 f = (row0 + r < n) ? __half22float2(bits2h(hh[(row0 + r) * 32 + c2]))
                                  : make_float2(0.f, 0.f);
        Xsh[r][2 * c2]     = f.x;
        Xsh[r][2 * c2 + 1] = f.y;
    }
    __syncthreads();
    float4 a0 = {0, 0, 0, 0}, a1 = {0, 0, 0, 0};
    #pragma unroll
    for (int k = 0; k < 64; k++) {
        float x0 = Xsh[ty][k];
        float x1 = Xsh[ty + 64][k];
        float4 w = Wsh4[k * 4 + tx];
        a0.x += x0 * w.x; a0.y += x0 * w.y; a0.z += x0 * w.z; a0.w += x0 * w.w;
        a1.x += x1 * w.x; a1.y += x1 * w.y; a1.z += x1 * w.z; a1.w += x1 * w.w;
    }
    int r0 = row0 + ty, r1 = row0 + ty + 64;
    if (r0 < n) {
        float di = g_dinv[r0];
        *reinterpret_cast<uint2*>(&g_hwh[r0 * 8 + 2 * tx]) =
            make_uint2(h2bits(__floats2half2_rn(a0.x * di, a0.y * di)),
                       h2bits(__floats2half2_rn(a0.z * di, a0.w * di)));
    }
    if (r1 < n) {
        float di = g_dinv[r1];
        *reinterpret_cast<uint2*>(&g_hwh[r1 * 8 + 2 * tx]) =
            make_uint2(h2bits(__floats2half2_rn(a1.x * di, a1.y * di)),
                       h2bits(__floats2half2_rn(a1.z * di, a1.w * di)));
    }
}

// layer-2 aggregation: one thread per (node, feature-pair); unroll 8
__global__ void k_agg2(float* __restrict__ out, const float* __restrict__ b2, int n) {
    int i = blockIdx.x * blockDim.x + threadIdx.x;
    if (i >= n * 8) return;
    int node = i >> 3;
    int f2   = i & 7;
    int beg = g_rowstart[node];
    int end = g_rowend[node];
    float ax0 = 0.f, ay0 = 0.f, ax1 = 0.f, ay1 = 0.f;
    float ax2 = 0.f, ay2 = 0.f, ax3 = 0.f, ay3 = 0.f;
    float ax4 = 0.f, ay4 = 0.f, ax5 = 0.f, ay5 = 0.f;
    float ax6 = 0.f, ay6 = 0.f, ax7 = 0.f, ay7 = 0.f;
    int j = beg;
    for (; j + 8 <= end; j += 8) {
        float2 f0 = __half22float2(g_hwh[g_csr[j]     * 8 + f2]);
        float2 f1 = __half22float2(g_hwh[g_csr[j + 1] * 8 + f2]);
        float2 f2v = __half22float2(g_hwh[g_csr[j + 2] * 8 + f2]);
        float2 f3 = __half22float2(g_hwh[g_csr[j + 3] * 8 + f2]);
        float2 f4 = __half22float2(g_hwh[g_csr[j + 4] * 8 + f2]);
        float2 f5 = __half22float2(g_hwh[g_csr[j + 5] * 8 + f2]);
        float2 f6 = __half22float2(g_hwh[g_csr[j + 6] * 8 + f2]);
        float2 f7 = __half22float2(g_hwh[g_csr[j + 7] * 8 + f2]);
        ax0 += f0.x; ay0 += f0.y; ax1 += f1.x; ay1 += f1.y;
        ax2 += f2v.x; ay2 += f2v.y; ax3 += f3.x; ay3 += f3.y;
        ax4 += f4.x; ay4 += f4.y; ax5 += f5.x; ay5 += f5.y;
        ax6 += f6.x; ay6 += f6.y; ax7 += f7.x; ay7 += f7.y;
    }
    for (; j + 4 <= end; j += 4) {
        float2 f0 = __half22float2(g_hwh[g_csr[j]     * 8 + f2]);
        float2 f1 = __half22float2(g_hwh[g_csr[j + 1] * 8 + f2]);
        float2 f2v = __half22float2(g_hwh[g_csr[j + 2] * 8 + f2]);
        float2 f3 = __half22float2(g_hwh[g_csr[j + 3] * 8 + f2]);
        ax0 += f0.x; ay0 += f0.y; ax1 += f1.x; ay1 += f1.y;
        ax2 += f2v.x; ay2 += f2v.y; ax3 += f3.x; ay3 += f3.y;
    }
    for (; j < end; j++) {
        float2 f = __half22float2(g_hwh[g_csr[j] * 8 + f2]);
        ax0 += f.x; ay0 += f.y;
    }
    float2 self = __half22float2(g_hwh[node * 8 + f2]);
    float di = g_dinv[node];
    float sx = ((ax0 + ax1) + (ax2 + ax3)) + ((ax4 + ax5) + (ax6 + ax7));
    float sy = ((ay0 + ay1) + (ay2 + ay3)) + ((ay4 + ay5) + (ay6 + ay7));
    float2 o = make_float2(di * (sx + self.x) + b2[2 * f2],
                           di * (sy + self.y) + b2[2 * f2 + 1]);
    *reinterpret_cast<float2*>(&out[node * 16 + 2 * f2]) = o;
}

extern "C" void kernel_launch(void* const* d_in, const int* in_sizes, int n_in,
                              void* d_out, int out_size) {
    const float* x  = (const float*)d_in[0];
    const void*  ei = (const void*)d_in[1];
    const float* W1 = (const float*)d_in[2];
    const float* b1 = (const float*)d_in[3];
    const float* W2 = (const float*)d_in[4];
    const float* b2 = (const float*)d_in[5];
    float* out = (float*)d_out;

    int n = in_sizes[0] / 64;   // 100000
    int e = in_sizes[1] / 2;    // 1600000
    if (n > MAXN) n = MAXN;
    if (e > MAXE) e = MAXE;
    int nb = (n + SB - 1) / SB;
    bool v4 = (e % 4) == 0;

    cudaStream_t s2;
    cudaEvent_t ev0, ev_scan, ev_scale;
    cudaStreamCreateWithFlags(&s2, cudaStreamNonBlocking);
    cudaEventCreateWithFlags(&ev0, cudaEventDisableTiming);
    cudaEventCreateWithFlags(&ev_scan, cudaEventDisableTiming);
    cudaEventCreateWithFlags(&ev_scale, cudaEventDisableTiming);

    const int T = 256;
    cudaEventRecord(ev0, 0);
    cudaStreamWaitEvent(s2, ev0, 0);
    // main edge pipeline (g_deg/g_ticket zeroed by fill of the PREVIOUS
    // replay; zero at module load for the first call)
    k_detect<<<8, 256>>>((const unsigned*)ei);                          // #1
    if (v4) k_deg4<<<(e / 4 + T - 1) / T, T>>>(ei, e, n);               // #2
    else    k_deg1<<<(e + T - 1) / T, T>>>(ei, e, n);
    k_scan <<<nb, SB>>>(n);                                             // #3
    cudaEventRecord(ev_scan, 0);
    if (v4) k_fill4<<<(e / 4 + T - 1) / T, T>>>(ei, e, n);              // #4 (profiled)
    else    k_fill1<<<(e + T - 1) / T, T>>>(ei, e, n);
    // s2: gemm1 executes from t=0; scale after gemm1 ∧ scan
    k_gemm1<<<(n + 127) / 128, dim3(16, 16), 0, s2>>>(x, W1, n);        // #5
    cudaStreamWaitEvent(s2, ev_scan, 0);
    k_scale<<<(n * 16 + T - 1) / T, T, 0, s2>>>(n);                     // #6
    cudaEventRecord(ev_scale, s2);
    cudaStreamWaitEvent(0, ev_scale, 0);
    k_agg1 <<<(n * 32 + T - 1) / T, T>>>(b1, n);                        // #7
    k_gemm2<<<(n + 127) / 128, dim3(4, 64)>>>(W2, n);                   // #8
    k_agg2 <<<(n * 8 + T - 1) / T, T>>>(out, b2, n);                    // #9
}

// round 15
// speedup vs baseline: 1.0734x; 1.0734x over previous
#include <cuda_runtime.h>
#include <cuda_fp16.h>

#define MAXN 100000
#define MAXE 1600000
#define SB 512

typedef unsigned long long u64t;

// packed f32x2 ops (sm_103a double-rate FP32 — only via PTX)
#define FMA2(d, a, b, c) \
    asm("fma.rn.f32x2 %0, %1, %2, %3;" : "=l"(d) : "l"(a), "l"(b), "l"(c))
#define PK2(d, lo, hi) \
    asm("mov.b64 %0, {%1, %2};" : "=l"(d) : "r"(__float_as_uint(lo)), "r"(__float_as_uint(hi)))

__device__ __forceinline__ float lo2(u64t v) { return __uint_as_float((unsigned)(v & 0xffffffffu)); }
__device__ __forceinline__ float hi2(u64t v) { return __uint_as_float((unsigned)(v >> 32)); }

__device__ __forceinline__ unsigned h2bits(__half2 h) {
    union { __half2 h; unsigned u; } cv; cv.h = h; return cv.u;
}
__device__ __forceinline__ __half2 bits2h(unsigned u) {
    union { unsigned u; __half2 h; } cv; cv.u = u; return cv.h;
}

// Scratch (device globals — no allocation allowed). g_deg/g_ticket are
// zero at module load; k_fill re-zeroes them each replay (tail-zeroing).
// g_xwh/g_hwh have ONE EXTRA row (index n) that is never written -> stays
// zero; predicated gathers clamp out-of-range lanes to it.
__device__ int     g_any = 0;          // sticky: 1 => edge buffer is int32
__device__ int     g_ticket;
__device__ int     g_deg[MAXN];
__device__ float   g_dinv[MAXN];
__device__ int     g_rank[MAXE];
__device__ int     g_csr[MAXE];
__device__ int     g_rowstart[MAXN];
__device__ int     g_rowend[MAXN];
__device__ __half2 g_xwh[(MAXN + 1) * 32];   // x @ W1 (fp16); dinv-scaled by k_scale
__device__ __half2 g_hh [MAXN * 32];         // hidden after relu (fp16)
__device__ __half2 g_hwh[(MAXN + 1) * 8];    // (h @ W2) * dinv[row], fp16

// ---------------------------------------------------------------------------
// detect: sticky dtype detect (int64 LE => odd 32-bit words all zero)
__global__ void k_detect(const unsigned* __restrict__ w) {
    int i = blockIdx.x * blockDim.x + threadIdx.x;
    if (i < 2048 && w[2 * i + 1] != 0u) atomicOr(&g_any, 1);
}

// deg (x4 MLP): 4 edges/thread — vector dst decode, 4 atomics, int4 rank store
__global__ void k_deg4(const void* __restrict__ eiv, int e, int n) {
    int q = blockIdx.x * blockDim.x + threadIdx.x;
    if (q * 4 >= e) return;
    int d0, d1, d2, d3;
    if (g_any == 0) {
        const longlong4* p = (const longlong4*)((const long long*)eiv + e);
        longlong4 v = p[q];
        d0 = (int)v.x; d1 = (int)v.y; d2 = (int)v.z; d3 = (int)v.w;
    } else {
        const int4* p = (const int4*)((const int*)eiv + e);
        int4 v = p[q];
        d0 = v.x; d1 = v.y; d2 = v.z; d3 = v.w;
    }
    int4 r;
    r.x = ((unsigned)d0 < (unsigned)n) ? atomicAdd(&g_deg[d0], 1) : -1;
    r.y = ((unsigned)d1 < (unsigned)n) ? atomicAdd(&g_deg[d1], 1) : -1;
    r.z = ((unsigned)d2 < (unsigned)n) ? atomicAdd(&g_deg[d2], 1) : -1;
    r.w = ((unsigned)d3 < (unsigned)n) ? atomicAdd(&g_deg[d3], 1) : -1;
    *reinterpret_cast<int4*>(&g_rank[q * 4]) = r;
}

__global__ void k_deg1(const void* __restrict__ eiv, int e, int n) {
    int i = blockIdx.x * blockDim.x + threadIdx.x;
    if (i >= e) return;
    int d;
    if (g_any == 0) d = (int)((const long long*)eiv)[(long long)e + i];
    else            d = ((const int*)eiv)[e + i];
    if ((unsigned)d < (unsigned)n) g_rank[i] = atomicAdd(&g_deg[d], 1);
    else                           g_rank[i] = -1;
}

// scan: block-local scan + one atomic ticket per block; writes rowstart+rowend
__global__ void k_scan(int n) {
    __shared__ int sh[SB];
    __shared__ int s_base;
    int t = threadIdx.x;
    int g = blockIdx.x * SB + t;
    int deg = (g < n) ? g_deg[g] : 0;
    sh[t] = deg;
    __syncthreads();
    for (int off = 1; off < SB; off <<= 1) {
        int tmp = (t >= off) ? sh[t - off] : 0;
        __syncthreads();
        if (t >= off) sh[t] += tmp;
        __syncthreads();
    }
    int incl = sh[t];
    if (t == SB - 1) s_base = atomicAdd(&g_ticket, incl);
    __syncthreads();
    if (g < n) {
        int end = s_base + incl;
        g_rowstart[g] = end - deg;
        g_rowend[g]   = end;
        g_dinv[g]     = rsqrtf((float)deg + 1.0f);
    }
}

// fill (x4 MLP) + tail-zero deg/ticket for next replay  (profiled slot #4)
__global__ void k_fill4(const void* __restrict__ eiv, int e, int n) {
    int q = blockIdx.x * blockDim.x + threadIdx.x;
    if (q < n) g_deg[q] = 0;            // e/4 = 400k threads cover n = 100k
    if (q == 0) g_ticket = 0;
    if (q * 4 >= e) return;
    int4 r = *reinterpret_cast<const int4*>(&g_rank[q * 4]);
    int s0, s1, s2, s3, d0, d1, d2, d3;
    if (g_any == 0) {
        const longlong4* ps = (const longlong4*)eiv;
        const longlong4* pd = (const longlong4*)((const long long*)eiv + e);
        longlong4 vs = ps[q];
        longlong4 vd = pd[q];
        s0 = (int)vs.x; s1 = (int)vs.y; s2 = (int)vs.z; s3 = (int)vs.w;
        d0 = (int)vd.x; d1 = (int)vd.y; d2 = (int)vd.z; d3 = (int)vd.w;
    } else {
        const int4* ps = (const int4*)eiv;
        const int4* pd = (const int4*)((const int*)eiv + e);
        int4 vs = ps[q];
        int4 vd = pd[q];
        s0 = vs.x; s1 = vs.y; s2 = vs.z; s3 = vs.w;
        d0 = vd.x; d1 = vd.y; d2 = vd.z; d3 = vd.w;
    }
    if ((unsigned)s0 >= (unsigned)n) s0 = 0;
    if ((unsigned)s1 >= (unsigned)n) s1 = 0;
    if ((unsigned)s2 >= (unsigned)n) s2 = 0;
    if ((unsigned)s3 >= (unsigned)n) s3 = 0;
    int b0 = (r.x >= 0) ? g_rowstart[d0] : 0;
    int b1 = (r.y >= 0) ? g_rowstart[d1] : 0;
    int b2 = (r.z >= 0) ? g_rowstart[d2] : 0;
    int b3 = (r.w >= 0) ? g_rowstart[d3] : 0;
    if (r.x >= 0) g_csr[b0 + r.x] = s0;
    if (r.y >= 0) g_csr[b1 + r.y] = s1;
    if (r.z >= 0) g_csr[b2 + r.z] = s2;
    if (r.w >= 0) g_csr[b3 + r.w] = s3;
}

__global__ void k_fill1(const void* __restrict__ eiv, int e, int n) {
    int i = blockIdx.x * blockDim.x + threadIdx.x;
    if (i < n) g_deg[i] = 0;
    if (i == 0) g_ticket = 0;
    if (i >= e) return;
    int r = g_rank[i];
    if (r < 0) return;
    int s, d;
    if (g_any == 0) {
        const long long* ei = (const long long*)eiv;
        s = (int)ei[i];
        d = (int)ei[(long long)e + i];
    } else {
        const int* ei = (const int*)eiv;
        s = ei[i];
        d = ei[e + i];
    }
    if ((unsigned)s >= (unsigned)n) s = 0;
    g_csr[g_rowstart[d] + r] = s;
}

// GEMM1 via packed f32x2; stores UNSCALED fp16 (no dinv dependency)
__global__ void __launch_bounds__(256) k_gemm1(const float* __restrict__ x,
                                               const float* __restrict__ W, int n) {
    __shared__ float2 Xt2[64][66];
    __shared__ float4 Wsh4[64 * 16];
    int tx = threadIdx.x;
    int ty = threadIdx.y;
    int tid = ty * 16 + tx;
    int row0 = blockIdx.x * 128;
    const float4* x4 = (const float4*)x;
    const float4* W4 = (const float4*)W;
    for (int i = tid; i < 1024; i += 256) Wsh4[i] = W4[i];
    float4 z = make_float4(0.f, 0.f, 0.f, 0.f);
    for (int i = tid; i < 1024; i += 256) {
        int p = i >> 4, c4 = i & 15;
        int r = row0 + 2 * p;
        float4 v0 = (r     < n) ? x4[(r)     * 16 + c4] : z;
        float4 v1 = (r + 1 < n) ? x4[(r + 1) * 16 + c4] : z;
        Xt2[c4 * 4 + 0][p] = make_float2(v0.x, v1.x);
        Xt2[c4 * 4 + 1][p] = make_float2(v0.y, v1.y);
        Xt2[c4 * 4 + 2][p] = make_float2(v0.z, v1.z);
        Xt2[c4 * 4 + 3][p] = make_float2(v0.w, v1.w);
    }
    __syncthreads();
    u64t acc[4][4];
    #pragma unroll
    for (int p = 0; p < 4; p++)
        #pragma unroll
        for (int c = 0; c < 4; c++) acc[p][c] = 0ull;
    int pbase = ty * 4;
    #pragma unroll 16
    for (int k = 0; k < 64; k++) {
        float4 w = Wsh4[k * 16 + tx];
        u64t w0, w1, w2, w3;
        PK2(w0, w.x, w.x);
        PK2(w1, w.y, w.y);
        PK2(w2, w.z, w.z);
        PK2(w3, w.w, w.w);
        #pragma unroll
        for (int p = 0; p < 4; p++) {
            u64t xv = *reinterpret_cast<const u64t*>(&Xt2[k][pbase + p]);
            FMA2(acc[p][0], xv, w0, acc[p][0]);
            FMA2(acc[p][1], xv, w1, acc[p][1]);
            FMA2(acc[p][2], xv, w2, acc[p][2]);
            FMA2(acc[p][3], xv, w3, acc[p][3]);
        }
    }
    #pragma unroll
    for (int p = 0; p < 4; p++) {
        int re = row0 + 2 * (pbase + p);
        int ro = re + 1;
        if (re < n) {
            __half2 h0 = __floats2half2_rn(lo2(acc[p][0]), lo2(acc[p][1]));
            __half2 h1 = __floats2half2_rn(lo2(acc[p][2]), lo2(acc[p][3]));
            *reinterpret_cast<uint2*>(&g_xwh[re * 32 + 2 * tx]) =
                make_uint2(h2bits(h0), h2bits(h1));
        }
        if (ro < n) {
            __half2 h0 = __floats2half2_rn(hi2(acc[p][0]), hi2(acc[p][1]));
            __half2 h1 = __floats2half2_rn(hi2(acc[p][2]), hi2(acc[p][3]));
            *reinterpret_cast<uint2*>(&g_xwh[ro * 32 + 2 * tx]) =
                make_uint2(h2bits(h0), h2bits(h1));
        }
    }
}

// scale messages by dinv[row] in place (off critical path: overlaps fill)
__global__ void k_scale(int n) {
    int i = blockIdx.x * blockDim.x + threadIdx.x;
    if (i >= n * 16) return;
    int row = i >> 4;
    float di = g_dinv[row];
    uint2 v = ((uint2*)g_xwh)[i];
    float2 fa = __half22float2(bits2h(v.x));
    float2 fb = __half22float2(bits2h(v.y));
    fa.x *= di; fa.y *= di; fb.x *= di; fb.y *= di;
    ((uint2*)g_xwh)[i] = make_uint2(h2bits(__floats2half2_rn(fa.x, fa.y)),
                                    h2bits(__floats2half2_rn(fb.x, fb.y)));
}

// layer-1 aggregation: one warp per node; predicated 4-wide gather (no tail):
// out-of-range lanes clamp to zero-row n.
__global__ void k_agg1(const float* __restrict__ b1, int n) {
    int warp = (blockIdx.x * blockDim.x + threadIdx.x) >> 5;
    int lane = threadIdx.x & 31;
    if (warp >= n) return;
    int beg = g_rowstart[warp];
    int end = g_rowend[warp];
    float ax0 = 0.f, ay0 = 0.f, ax1 = 0.f, ay1 = 0.f;
    float ax2 = 0.f, ay2 = 0.f, ax3 = 0.f, ay3 = 0.f;
    for (int j = beg; j < end; j += 4) {
        int s0 = g_csr[j];
        int s1 = (j + 1 < end) ? g_csr[j + 1] : n;
        int s2 = (j + 2 < end) ? g_csr[j + 2] : n;
        int s3 = (j + 3 < end) ? g_csr[j + 3] : n;
        float2 f0 = __half22float2(g_xwh[s0 * 32 + lane]);
        float2 f1 = __half22float2(g_xwh[s1 * 32 + lane]);
        float2 f2 = __half22float2(g_xwh[s2 * 32 + lane]);
        float2 f3 = __half22float2(g_xwh[s3 * 32 + lane]);
        ax0 += f0.x; ay0 += f0.y;
        ax1 += f1.x; ay1 += f1.y;
        ax2 += f2.x; ay2 += f2.y;
        ax3 += f3.x; ay3 += f3.y;
    }
    float2 self = __half22float2(g_xwh[warp * 32 + lane]);
    float di = g_dinv[warp];
    float vx = di * ((ax0 + ax1) + (ax2 + ax3) + self.x) + b1[2 * lane];
    float vy = di * ((ay0 + ay1) + (ay2 + ay3) + self.y) + b1[2 * lane + 1];
    vx = vx > 0.f ? vx : 0.f;
    vy = vy > 0.f ? vy : 0.f;
    g_hh[warp * 32 + lane] = __floats2half2_rn(vx, vy);
}

// GEMM2: g_hwh = fp16((h @ W2) * dinv[row]); 128-row tile, 2 rows/thread
__global__ void k_gemm2(const float* __restrict__ W, int n) {
    __shared__ float4 Wsh4[64 * 4];
    __shared__ float  Xsh[128][65];
    int tx = threadIdx.x;
    int ty = threadIdx.y;
    int tid = ty * 4 + tx;
    int row0 = blockIdx.x * 128;
    const float4* W4 = (const float4*)W;
    for (int i = tid; i < 256; i += 256) Wsh4[i] = W4[i];
    const unsigned* hh = (const unsigned*)g_hh;
    for (int i = tid; i < 4096; i += 256) {
        int r = i >> 5, c2 = i & 31;
        float2 f = (row0 + r < n) ? __half22float2(bits2h(hh[(row0 + r) * 32 + c2]))
                                  : make_float2(0.f, 0.f);
        Xsh[r][2 * c2]     = f.x;
        Xsh[r][2 * c2 + 1] = f.y;
    }
    __syncthreads();
    float4 a0 = {0, 0, 0, 0}, a1 = {0, 0, 0, 0};
    #pragma unroll
    for (int k = 0; k < 64; k++) {
        float x0 = Xsh[ty][k];
        float x1 = Xsh[ty + 64][k];
        float4 w = Wsh4[k * 4 + tx];
        a0.x += x0 * w.x; a0.y += x0 * w.y; a0.z += x0 * w.z; a0.w += x0 * w.w;
        a1.x += x1 * w.x; a1.y += x1 * w.y; a1.z += x1 * w.z; a1.w += x1 * w.w;
    }
    int r0 = row0 + ty, r1 = row0 + ty + 64;
    if (r0 < n) {
        float di = g_dinv[r0];
        *reinterpret_cast<uint2*>(&g_hwh[r0 * 8 + 2 * tx]) =
            make_uint2(h2bits(__floats2half2_rn(a0.x * di, a0.y * di)),
                       h2bits(__floats2half2_rn(a0.z * di, a0.w * di)));
    }
    if (r1 < n) {
        float di = g_dinv[r1];
        *reinterpret_cast<uint2*>(&g_hwh[r1 * 8 + 2 * tx]) =
            make_uint2(h2bits(__floats2half2_rn(a1.x * di, a1.y * di)),
                       h2bits(__floats2half2_rn(a1.z * di, a1.w * di)));
    }
}

// layer-2 aggregation: one thread per (node, feature-pair); predicated 4-wide
__global__ void k_agg2(float* __restrict__ out, const float* __restrict__ b2, int n) {
    int i = blockIdx.x * blockDim.x + threadIdx.x;
    if (i >= n * 8) return;
    int node = i >> 3;
    int f2   = i & 7;
    int beg = g_rowstart[node];
    int end = g_rowend[node];
    float ax0 = 0.f, ay0 = 0.f, ax1 = 0.f, ay1 = 0.f;
    float ax2 = 0.f, ay2 = 0.f, ax3 = 0.f, ay3 = 0.f;
    for (int j = beg; j < end; j += 4) {
        int s0 = g_csr[j];
        int s1 = (j + 1 < end) ? g_csr[j + 1] : n;
        int s2 = (j + 2 < end) ? g_csr[j + 2] : n;
        int s3 = (j + 3 < end) ? g_csr[j + 3] : n;
        float2 f0 = __half22float2(g_hwh[s0 * 8 + f2]);
        float2 f1 = __half22float2(g_hwh[s1 * 8 + f2]);
        float2 fv = __half22float2(g_hwh[s2 * 8 + f2]);
        float2 f3 = __half22float2(g_hwh[s3 * 8 + f2]);
        ax0 += f0.x; ay0 += f0.y;
        ax1 += f1.x; ay1 += f1.y;
        ax2 += fv.x; ay2 += fv.y;
        ax3 += f3.x; ay3 += f3.y;
    }
    float2 self = __half22float2(g_hwh[node * 8 + f2]);
    float di = g_dinv[node];
    float2 o = make_float2(di * ((ax0 + ax1) + (ax2 + ax3) + self.x) + b2[2 * f2],
                           di * ((ay0 + ay1) + (ay2 + ay3) + self.y) + b2[2 * f2 + 1]);
    *reinterpret_cast<float2*>(&out[node * 16 + 2 * f2]) = o;
}

extern "C" void kernel_launch(void* const* d_in, const int* in_sizes, int n_in,
                              void* d_out, int out_size) {
    const float* x  = (const float*)d_in[0];
    const void*  ei = (const void*)d_in[1];
    const float* W1 = (const float*)d_in[2];
    const float* b1 = (const float*)d_in[3];
    const float* W2 = (const float*)d_in[4];
    const float* b2 = (const float*)d_in[5];
    float* out = (float*)d_out;

    int n = in_sizes[0] / 64;   // 100000
    int e = in_sizes[1] / 2;    // 1600000
    if (n > MAXN) n = MAXN;
    if (e > MAXE) e = MAXE;
    int nb = (n + SB - 1) / SB;
    bool v4 = (e % 4) == 0;

    cudaStream_t s2;
    cudaEvent_t ev0, ev_scan, ev_scale;
    cudaStreamCreateWithFlags(&s2, cudaStreamNonBlocking);
    cudaEventCreateWithFlags(&ev0, cudaEventDisableTiming);
    cudaEventCreateWithFlags(&ev_scan, cudaEventDisableTiming);
    cudaEventCreateWithFlags(&ev_scale, cudaEventDisableTiming);

    const int T = 256;
    cudaEventRecord(ev0, 0);
    cudaStreamWaitEvent(s2, ev0, 0);
    // main edge pipeline (g_deg/g_ticket zeroed by previous replay's fill)
    k_detect<<<8, 256>>>((const unsigned*)ei);                          // #1
    if (v4) k_deg4<<<(e / 4 + T - 1) / T, T>>>(ei, e, n);               // #2
    else    k_deg1<<<(e + T - 1) / T, T>>>(ei, e, n);
    k_scan <<<nb, SB>>>(n);                                             // #3
    cudaEventRecord(ev_scan, 0);
    if (v4) k_fill4<<<(e / 4 + T - 1) / T, T>>>(ei, e, n);              // #4 (profiled)
    else    k_fill1<<<(e + T - 1) / T, T>>>(ei, e, n);
    // s2: gemm1 executes from t=0; scale after gemm1 ∧ scan
    k_gemm1<<<(n + 127) / 128, dim3(16, 16), 0, s2>>>(x, W1, n);        // #5
    cudaStreamWaitEvent(s2, ev_scan, 0);
    k_scale<<<(n * 16 + T - 1) / T, T, 0, s2>>>(n);                     // #6
    cudaEventRecord(ev_scale, s2);
    cudaStreamWaitEvent(0, ev_scale, 0);
    k_agg1 <<<(n * 32 + T - 1) / T, T>>>(b1, n);                        // #7
    k_gemm2<<<(n + 127) / 128, dim3(4, 64)>>>(W2, n);                   // #8
    k_agg2 <<<(n * 8 + T - 1) / T, T>>>(out, b2, n);                    // #9
}